// round 8
// baseline (speedup 1.0000x reference)
#include <cuda_runtime.h>

#define Dm 1024
#define MAXB 8
#define TC 16           // tokens per chunk in k3 (S=2048 -> 128 chunks)
#define MAXCH 128

// ---------------- scratch (static device globals) ---------------------------
__device__ float g_q0[MAXB * Dm];              // Wq accumulator (init bq)
__device__ float g_u[MAXB * Dm];
__device__ float g_xw[MAXB * Dm];              // written fully by merge
__device__ float g_r[MAXB * Dm];
__device__ float g_accV[MAXB * Dm];            // Wv accumulator (init bv + x0)
__device__ float g_accD[MAXB * Dm];            // Wd accumulator (init bd)
__device__ float g_pm[MAXB * MAXCH];
__device__ float g_ps[MAXB * MAXCH];
__device__ float g_pacc[MAXB * MAXCH * Dm];    // 4 MB

// ---------------- block reductions ------------------------------------------
__device__ __forceinline__ float blk_reduce(float v, volatile float* sbuf) {
    int lane = threadIdx.x & 31, w = threadIdx.x >> 5;
#pragma unroll
    for (int o = 16; o; o >>= 1) v += __shfl_xor_sync(0xffffffffu, v, o);
    __syncthreads();
    if (lane == 0) sbuf[w] = v;
    __syncthreads();
    int nw = blockDim.x >> 5;
    if (w == 0) {
        float r = (lane < nw) ? sbuf[lane] : 0.f;
#pragma unroll
        for (int o = 16; o; o >>= 1) r += __shfl_xor_sync(0xffffffffu, r, o);
        if (lane == 0) sbuf[0] = r;
    }
    __syncthreads();
    return sbuf[0];
}

__device__ __forceinline__ float blk_rmax(float v, volatile float* sbuf) {
    int lane = threadIdx.x & 31, w = threadIdx.x >> 5;
#pragma unroll
    for (int o = 16; o; o >>= 1) v = fmaxf(v, __shfl_xor_sync(0xffffffffu, v, o));
    __syncthreads();
    if (lane == 0) sbuf[w] = v;
    __syncthreads();
    int nw = blockDim.x >> 5;
    if (w == 0) {
        float r = (lane < nw) ? sbuf[lane] : -1e30f;
#pragma unroll
        for (int o = 16; o; o >>= 1) r = fmaxf(r, __shfl_xor_sync(0xffffffffu, r, o));
        if (lane == 0) sbuf[0] = r;
    }
    __syncthreads();
    return sbuf[0];
}

// ---------------- kinit: seed accumulators -----------------------------------
__global__ void kinit(const float* __restrict__ x, long xstride,
                      const float* __restrict__ bq,
                      const float* __restrict__ bv,
                      const float* __restrict__ bd, int B) {
    int idx = blockIdx.x * 256 + threadIdx.x;
    if (idx < B * Dm) {
        int j = idx & (Dm - 1), b = idx >> 10;
        g_q0[idx]   = bq[j];
        g_accV[idx] = bv[j] + x[(long)b * xstride + j];
        g_accD[idx] = bd[j];
    }
}

// ---------------- PDL skinny GEMV: acc[b,j] += A[b,d0:d0+32] @ W -------------
// grid (4, 32), block 256. W tile preloaded to regs BEFORE gridsync (overlap).
__global__ void __launch_bounds__(256) gemv_pdl(const float* __restrict__ A,
                                                long astride,
                                                const float* __restrict__ W,
                                                float* __restrict__ accout, int B) {
    __shared__ float as[MAXB][32];
    int j  = blockIdx.x * 256 + threadIdx.x;
    int d0 = blockIdx.y * 32;
    float wv[32];
#pragma unroll
    for (int dd = 0; dd < 32; dd++) wv[dd] = W[(long)(d0 + dd) * Dm + j];
    cudaGridDependencySynchronize();
    {
        int b = threadIdx.x >> 5, dd = threadIdx.x & 31;
        as[b][dd] = (b < B) ? A[(long)b * astride + d0 + dd] : 0.f;
    }
    __syncthreads();
    float acc[MAXB];
#pragma unroll
    for (int b = 0; b < MAXB; b++) acc[b] = 0.f;
#pragma unroll
    for (int dd = 0; dd < 32; dd++) {
#pragma unroll
        for (int b = 0; b < MAXB; b++) acc[b] = fmaf(as[b][dd], wv[dd], acc[b]);
    }
    for (int b = 0; b < B; b++)
        atomicAdd(&accout[(long)b * Dm + j], acc[b]);
}

// ---------------- u[b,d] = Wk[d,:] . q0[b,:] ---------------------------------
// 128 blocks x 8 warps (1 row each). Wk row preloaded to regs before gridsync.
__global__ void __launch_bounds__(256) k2_u(const float* __restrict__ Wk,
                                            const float* __restrict__ q0g,
                                            float* __restrict__ u) {
    __shared__ float4 q0s[MAXB * 256];               // 32 KB
    int wid = threadIdx.x >> 5, lane = threadIdx.x & 31;
    int d = blockIdx.x * 8 + wid;
    const float4* wrow = (const float4*)(Wk + (long)d * Dm);
    float4 wv[8];
#pragma unroll
    for (int i = 0; i < 8; i++) wv[i] = wrow[lane + 32 * i];
    cudaGridDependencySynchronize();
    for (int i = threadIdx.x; i < MAXB * 256; i += 256)
        q0s[i] = ((const float4*)q0g)[i];
    __syncthreads();
    float acc[MAXB];
#pragma unroll
    for (int b = 0; b < MAXB; b++) acc[b] = 0.f;
#pragma unroll
    for (int i = 0; i < 8; i++) {
#pragma unroll
        for (int b = 0; b < MAXB; b++) {
            float4 q = q0s[b * 256 + lane + 32 * i];
            acc[b] += wv[i].x * q.x + wv[i].y * q.y + wv[i].z * q.z + wv[i].w * q.w;
        }
    }
#pragma unroll
    for (int b = 0; b < MAXB; b++)
#pragma unroll
        for (int o = 16; o; o >>= 1)
            acc[b] += __shfl_xor_sync(0xffffffffu, acc[b], o);
    if (lane == 0)
#pragma unroll
        for (int b = 0; b < MAXB; b++) u[(long)b * Dm + d] = acc[b];
}

// ---------------- k3: two-phase streaming, TC=16, grid (128,8) --------------
// Pre-sync: prefetch this block's 64 KB x-chunk to L2 (x independent of deps).
__global__ void __launch_bounds__(256) k3_stream(const float* __restrict__ x,
                                                 const float* __restrict__ u,
                                                 float* __restrict__ pm,
                                                 float* __restrict__ ps,
                                                 float* __restrict__ pacc,
                                                 int S, int nch) {
    int b = blockIdx.y, ch = blockIdx.x;
    int t0 = ch * TC;
    int tid = threadIdx.x;
    __shared__ float4 us[256];
    __shared__ float sc[TC];
    __shared__ float red[2];

    const float4* xb = (const float4*)(x + (long)b * S * Dm);
    const float4* xr0 = xb + (long)t0 * 256;
    // prefetch 64 KB chunk: 256 threads x 2 lines of 128 B
    {
        const char* base = (const char*)xr0 + tid * 256;
        asm volatile("prefetch.global.L2 [%0];" :: "l"(base));
        asm volatile("prefetch.global.L2 [%0];" :: "l"(base + 128));
    }
    cudaGridDependencySynchronize();

    us[tid] = ((const float4*)(u + (long)b * Dm))[tid];
    __syncthreads();

    int wid = tid >> 5, lane = tid & 31;
#pragma unroll
    for (int k = 0; k < 2; k++) {
        int tl = wid * 2 + k;
        const float4* xr = xb + (long)(t0 + tl) * 256;
        float a = 0.f;
#pragma unroll
        for (int i = 0; i < 8; i++) {
            float4 xv = xr[lane + 32 * i];
            float4 uv = us[lane + 32 * i];
            a += xv.x * uv.x + xv.y * uv.y + xv.z * uv.z + xv.w * uv.w;
        }
#pragma unroll
        for (int o = 16; o; o >>= 1) a += __shfl_xor_sync(0xffffffffu, a, o);
        if (lane == 0) sc[tl] = a * 0.03125f;        // 1/sqrt(1024)
    }
    __syncthreads();

    if (tid < 32) {
        float v = (tid < TC) ? sc[tid] : -1e30f;
        float m = v;
#pragma unroll
        for (int o = 16; o; o >>= 1) m = fmaxf(m, __shfl_xor_sync(0xffffffffu, m, o));
        float p = __expf(v - m);
        float s = p;
#pragma unroll
        for (int o = 16; o; o >>= 1) s += __shfl_xor_sync(0xffffffffu, s, o);
        if (tid < TC) sc[tid] = p;
        if (tid == 0) { red[0] = m; red[1] = s; }
    }
    __syncthreads();

    float4 acc = make_float4(0.f, 0.f, 0.f, 0.f);
#pragma unroll 4
    for (int t = 0; t < TC; t++) {
        float p = sc[t];
        float4 xv = xr0[(long)t * 256 + tid];
        acc.x = fmaf(p, xv.x, acc.x);
        acc.y = fmaf(p, xv.y, acc.y);
        acc.z = fmaf(p, xv.z, acc.z);
        acc.w = fmaf(p, xv.w, acc.w);
    }
    long ci = (long)b * nch + ch;
    ((float4*)pacc)[ci * 256 + tid] = acc;
    if (tid == 0) { pm[ci] = red[0]; ps[ci] = red[1]; }
}

// ---------------- merge chunk partials -> xw[b,:] (parallel over j) ---------
// grid (B, 16), block 128; nch = 128.
__global__ void __launch_bounds__(128) k4a_merge(const float* __restrict__ pm,
                                                 const float* __restrict__ ps,
                                                 const float* __restrict__ pacc,
                                                 float* __restrict__ xw, int nch) {
    __shared__ float f[MAXCH];
    __shared__ float4 partial[8][16];
    __shared__ float sbuf[32];
    int b = blockIdx.x, jc = blockIdx.y;
    int tid = threadIdx.x;
    cudaGridDependencySynchronize();

    float v = (tid < nch) ? pm[(long)b * nch + tid] : -1e30f;
    float M = blk_rmax(v, sbuf);
    float e = (tid < nch) ? __expf(v - M) : 0.f;
    if (tid < nch) f[tid] = e;
    float s = blk_reduce((tid < nch) ? e * ps[(long)b * nch + tid] : 0.f, sbuf);
    float sinv = 1.f / s;
    __syncthreads();

    int jj = tid & 15, cp = tid >> 4;                // 16 j4 x 8 partitions
    int j4 = jc * 16 + jj;
    const float4* pa = (const float4*)pacc;
    float4 acc = make_float4(0.f, 0.f, 0.f, 0.f);
    for (int c = cp; c < nch; c += 8) {
        float fc = f[c];
        float4 pv = pa[((long)b * nch + c) * 256 + j4];
        acc.x = fmaf(fc, pv.x, acc.x);
        acc.y = fmaf(fc, pv.y, acc.y);
        acc.z = fmaf(fc, pv.z, acc.z);
        acc.w = fmaf(fc, pv.w, acc.w);
    }
    partial[cp][jj] = acc;
    __syncthreads();
    if (tid < 16) {
        float4 t = partial[0][tid];
#pragma unroll
        for (int p = 1; p < 8; p++) {
            float4 v4 = partial[p][tid];
            t.x += v4.x; t.y += v4.y; t.z += v4.z; t.w += v4.w;
        }
        t.x *= sinv; t.y *= sinv; t.z *= sinv; t.w *= sinv;
        ((float4*)xw)[b * 256 + jc * 16 + tid] = t;
    }
}

// ---------------- r = LN1(accV) ----------------------------------------------
__global__ void __launch_bounds__(1024) k_ln1(const float* __restrict__ acc,
                                              const float* __restrict__ g1,
                                              const float* __restrict__ b1,
                                              float* __restrict__ r) {
    int b = blockIdx.x, j = threadIdx.x;
    __shared__ float sbuf[32];
    float gg = g1[j], bb = b1[j];
    cudaGridDependencySynchronize();
    float v = acc[(long)b * Dm + j];
    float sum = blk_reduce(v, sbuf);
    float sq  = blk_reduce(v * v, sbuf);
    float mu  = sum * (1.f / Dm);
    float var = sq * (1.f / Dm) - mu * mu;
    float rstd = rsqrtf(var + 1e-5f);
    r[(long)b * Dm + j] = (v - mu) * rstd * gg + bb;
}

// ---------------- h = LN2(relu(accD) + r); logits = h@Wc + bc ----------------
__global__ void __launch_bounds__(1024) k_ln2(const float* __restrict__ acc,
                                              const float* __restrict__ r,
                                              const float* __restrict__ g2,
                                              const float* __restrict__ b2,
                                              const float* __restrict__ Wc,
                                              const float* __restrict__ bc,
                                              float* __restrict__ out) {
    int b = blockIdx.x, j = threadIdx.x;
    __shared__ float sbuf[32];
    float gg = g2[j], bb = b2[j];
    float w0 = Wc[j * 2 + 0], w1 = Wc[j * 2 + 1];
    cudaGridDependencySynchronize();
    float v = fmaxf(acc[(long)b * Dm + j], 0.f) + r[(long)b * Dm + j];
    float sum = blk_reduce(v, sbuf);
    float sq  = blk_reduce(v * v, sbuf);
    float mu  = sum * (1.f / Dm);
    float var = sq * (1.f / Dm) - mu * mu;
    float rstd = rsqrtf(var + 1e-5f);
    float h = (v - mu) * rstd * gg + bb;
    float l0 = blk_reduce(h * w0, sbuf);
    float l1 = blk_reduce(h * w1, sbuf);
    if (j == 0) {
        out[b * 2 + 0] = l0 + bc[0];
        out[b * 2 + 1] = l1 + bc[1];
    }
}

// ---------------- host --------------------------------------------------------
static void launch_ex(const void* fn, dim3 grid, dim3 block, void** args, bool pdl) {
    cudaLaunchConfig_t cfg = {};
    cfg.gridDim = grid;
    cfg.blockDim = block;
    cfg.dynamicSmemBytes = 0;
    cfg.stream = 0;
    cudaLaunchAttribute attr[1];
    attr[0].id = cudaLaunchAttributeProgrammaticStreamSerialization;
    attr[0].val.programmaticStreamSerializationAllowed = 1;
    cfg.attrs = attr;
    cfg.numAttrs = pdl ? 1 : 0;
    cudaLaunchKernelExC(&cfg, fn, args);
}

extern "C" void kernel_launch(void* const* d_in, const int* in_sizes, int n_in,
                              void* d_out, int out_size) {
    const float* x  = (const float*)d_in[0];
    const float* Wq = (const float*)d_in[1];
    const float* bq = (const float*)d_in[2];
    const float* Wk = (const float*)d_in[3];
    // d_in[4] = bk: constant over t in scores -> cancels in softmax; unused.
    const float* Wv = (const float*)d_in[5];
    const float* bv = (const float*)d_in[6];
    const float* Wd = (const float*)d_in[7];
    const float* bd = (const float*)d_in[8];
    const float* g1 = (const float*)d_in[9];
    const float* b1 = (const float*)d_in[10];
    const float* g2 = (const float*)d_in[11];
    const float* b2 = (const float*)d_in[12];
    const float* Wc = (const float*)d_in[13];
    const float* bc = (const float*)d_in[14];
    float* out = (float*)d_out;

    int  B   = out_size / 2;                       // 8
    long xsz = (long)in_sizes[0];
    int  S   = (int)(xsz / ((long)B * Dm));        // 2048
    int  nch = S / TC;                             // 128
    long xstride = (long)S * Dm;

    float *q0, *u, *xw, *r, *accV, *accD, *pm, *ps, *pacc;
    cudaGetSymbolAddress((void**)&q0,   g_q0);
    cudaGetSymbolAddress((void**)&u,    g_u);
    cudaGetSymbolAddress((void**)&xw,   g_xw);
    cudaGetSymbolAddress((void**)&r,    g_r);
    cudaGetSymbolAddress((void**)&accV, g_accV);
    cudaGetSymbolAddress((void**)&accD, g_accD);
    cudaGetSymbolAddress((void**)&pm,   g_pm);
    cudaGetSymbolAddress((void**)&ps,   g_ps);
    cudaGetSymbolAddress((void**)&pacc, g_pacc);

    // 1. seed accumulators
    {
        void* a[] = {(void*)&x, (void*)&xstride, (void*)&bq, (void*)&bv, (void*)&bd, (void*)&B};
        launch_ex((const void*)kinit, dim3((B * Dm + 255) / 256), dim3(256), a, false);
    }
    // 2. q0 += x0 @ Wq
    {
        void* a[] = {(void*)&x, (void*)&xstride, (void*)&Wq, (void*)&q0, (void*)&B};
        launch_ex((const void*)gemv_pdl, dim3(4, 32), dim3(256), a, true);
    }
    // 3. u = Wk @ q0
    {
        void* a[] = {(void*)&Wk, (void*)&q0, (void*)&u};
        launch_ex((const void*)k2_u, dim3(Dm / 8), dim3(256), a, true);
    }
    // 4. streaming attention partials (single pass over x)
    {
        void* a[] = {(void*)&x, (void*)&u, (void*)&pm, (void*)&ps, (void*)&pacc,
                     (void*)&S, (void*)&nch};
        launch_ex((const void*)k3_stream, dim3(nch, B), dim3(256), a, true);
    }
    // 5. merge -> xw
    {
        void* a[] = {(void*)&pm, (void*)&ps, (void*)&pacc, (void*)&xw, (void*)&nch};
        launch_ex((const void*)k4a_merge, dim3(B, 16), dim3(128), a, true);
    }
    // 6. accV += xw @ Wv
    {
        long st = Dm;
        void* a[] = {(void*)&xw, (void*)&st, (void*)&Wv, (void*)&accV, (void*)&B};
        launch_ex((const void*)gemv_pdl, dim3(4, 32), dim3(256), a, true);
    }
    // 7. r = LN1(accV)
    {
        void* a[] = {(void*)&accV, (void*)&g1, (void*)&b1, (void*)&r};
        launch_ex((const void*)k_ln1, dim3(B), dim3(1024), a, true);
    }
    // 8. accD += r @ Wd
    {
        long st = Dm;
        void* a[] = {(void*)&r, (void*)&st, (void*)&Wd, (void*)&accD, (void*)&B};
        launch_ex((const void*)gemv_pdl, dim3(4, 32), dim3(256), a, true);
    }
    // 9. out = LN2(relu(accD)+r) @ Wc + bc
    {
        void* a[] = {(void*)&accD, (void*)&r, (void*)&g2, (void*)&b2,
                     (void*)&Wc, (void*)&bc, (void*)&out};
        launch_ex((const void*)k_ln2, dim3(B), dim3(1024), a, true);
    }
}

// round 9
// speedup vs baseline: 1.1534x; 1.1534x over previous
#include <cuda_runtime.h>

#define Dm 1024
#define MAXB 8
#define SMAX 4096

// ---------------- scratch (static device globals; zero-initialized at load,
// and reset to zero by downstream consumers each run for graph-replay
// determinism) -----------------------------------------------------------------
__device__ float g_q0[MAXB * Dm];              // Wq accumulator (zeroed by k3a)
__device__ float g_u[MAXB * Dm];               // overwritten fully by k2_u
__device__ float g_xw[MAXB * Dm];              // k3b accumulator (zeroed by k_ln1)
__device__ float g_r[MAXB * Dm];               // overwritten fully by k_ln1
__device__ float g_accV[MAXB * Dm];            // Wv accumulator (zeroed by k_ln1)
__device__ float g_accD[MAXB * Dm];            // Wd accumulator (zeroed by k_ln2)
__device__ float g_sc[MAXB * SMAX];            // scores (overwritten by k3a)

// ---------------- block reductions ------------------------------------------
__device__ __forceinline__ float blk_reduce(float v, volatile float* sbuf) {
    int lane = threadIdx.x & 31, w = threadIdx.x >> 5;
#pragma unroll
    for (int o = 16; o; o >>= 1) v += __shfl_xor_sync(0xffffffffu, v, o);
    __syncthreads();
    if (lane == 0) sbuf[w] = v;
    __syncthreads();
    int nw = blockDim.x >> 5;
    if (w == 0) {
        float r = (lane < nw) ? sbuf[lane] : 0.f;
#pragma unroll
        for (int o = 16; o; o >>= 1) r += __shfl_xor_sync(0xffffffffu, r, o);
        if (lane == 0) sbuf[0] = r;
    }
    __syncthreads();
    return sbuf[0];
}

__device__ __forceinline__ float blk_rmax(float v, volatile float* sbuf) {
    int lane = threadIdx.x & 31, w = threadIdx.x >> 5;
#pragma unroll
    for (int o = 16; o; o >>= 1) v = fmaxf(v, __shfl_xor_sync(0xffffffffu, v, o));
    __syncthreads();
    if (lane == 0) sbuf[w] = v;
    __syncthreads();
    int nw = blockDim.x >> 5;
    if (w == 0) {
        float r = (lane < nw) ? sbuf[lane] : -1e30f;
#pragma unroll
        for (int o = 16; o; o >>= 1) r = fmaxf(r, __shfl_xor_sync(0xffffffffu, r, o));
        if (lane == 0) sbuf[0] = r;
    }
    __syncthreads();
    return sbuf[0];
}

// ---------------- PDL skinny GEMV: acc[b,j] += A[b,d0:d0+32] @ W -------------
// grid (4, 32), block 256. W tile preloaded to regs BEFORE gridsync (overlap).
// Target buffer must be zero on entry (module-load init / downstream reset).
__global__ void __launch_bounds__(256) gemv_pdl(const float* __restrict__ A,
                                                long astride,
                                                const float* __restrict__ W,
                                                float* __restrict__ accout, int B) {
    __shared__ float as[MAXB][32];
    int j  = blockIdx.x * 256 + threadIdx.x;
    int d0 = blockIdx.y * 32;
    float wv[32];
#pragma unroll
    for (int dd = 0; dd < 32; dd++) wv[dd] = W[(long)(d0 + dd) * Dm + j];
    cudaGridDependencySynchronize();
    {
        int b = threadIdx.x >> 5, dd = threadIdx.x & 31;
        as[b][dd] = (b < B) ? A[(long)b * astride + d0 + dd] : 0.f;
    }
    __syncthreads();
    float acc[MAXB];
#pragma unroll
    for (int b = 0; b < MAXB; b++) acc[b] = 0.f;
#pragma unroll
    for (int dd = 0; dd < 32; dd++) {
#pragma unroll
        for (int b = 0; b < MAXB; b++) acc[b] = fmaf(as[b][dd], wv[dd], acc[b]);
    }
    for (int b = 0; b < B; b++)
        atomicAdd(&accout[(long)b * Dm + j], acc[b]);
}

// ---------------- u[b,d] = Wk[d,:] . (q0[b,:] + bq) --------------------------
// 128 blocks x 8 warps (1 row each). Wk row preloaded to regs before gridsync.
__global__ void __launch_bounds__(256) k2_u(const float* __restrict__ Wk,
                                            const float* __restrict__ q0g,
                                            const float* __restrict__ bq,
                                            float* __restrict__ u) {
    __shared__ float4 q0s[MAXB * 256];               // 32 KB
    int wid = threadIdx.x >> 5, lane = threadIdx.x & 31;
    int d = blockIdx.x * 8 + wid;
    const float4* wrow = (const float4*)(Wk + (long)d * Dm);
    float4 wv[8];
#pragma unroll
    for (int i = 0; i < 8; i++) wv[i] = wrow[lane + 32 * i];
    cudaGridDependencySynchronize();
    for (int i = threadIdx.x; i < MAXB * 256; i += 256) {
        float4 q = ((const float4*)q0g)[i];
        float4 bb = ((const float4*)bq)[i & 255];
        q.x += bb.x; q.y += bb.y; q.z += bb.z; q.w += bb.w;
        q0s[i] = q;
    }
    __syncthreads();
    float acc[MAXB];
#pragma unroll
    for (int b = 0; b < MAXB; b++) acc[b] = 0.f;
#pragma unroll
    for (int i = 0; i < 8; i++) {
#pragma unroll
        for (int b = 0; b < MAXB; b++) {
            float4 q = q0s[b * 256 + lane + 32 * i];
            acc[b] += wv[i].x * q.x + wv[i].y * q.y + wv[i].z * q.z + wv[i].w * q.w;
        }
    }
#pragma unroll
    for (int b = 0; b < MAXB; b++)
#pragma unroll
        for (int o = 16; o; o >>= 1)
            acc[b] += __shfl_xor_sync(0xffffffffu, acc[b], o);
    if (lane == 0)
#pragma unroll
        for (int b = 0; b < MAXB; b++) u[(long)b * Dm + d] = acc[b];
}

// ---------------- k3a: pure score stream -------------------------------------
// grid (S/32, B), 256 thr: 8 warps x 4 tokens. u in registers, zero smem for x.
// Also resets q0 (safe: k2_u completed at gridsync).
__global__ void __launch_bounds__(256) k3a(const float* __restrict__ x,
                                           const float* __restrict__ ug,
                                           float* __restrict__ q0reset,
                                           float* __restrict__ sc, int S) {
    int b = blockIdx.y;
    int wid = threadIdx.x >> 5, lane = threadIdx.x & 31;
    int tbase = blockIdx.x * 32 + wid * 4;
    const float4* x0 = (const float4*)x + ((long)b * S + tbase) * 256;
#pragma unroll
    for (int i = 0; i < 8; i++)
        asm volatile("prefetch.global.L2 [%0];" :: "l"(x0 + lane + 32 * i));
    cudaGridDependencySynchronize();
    if (blockIdx.x == 0)                              // zero q0[b,:] for next run
        ((float4*)q0reset)[b * 256 + threadIdx.x] = make_float4(0.f, 0.f, 0.f, 0.f);
    const float4* ub = (const float4*)(ug + (long)b * Dm);
    float4 uv[8];
#pragma unroll
    for (int i = 0; i < 8; i++) uv[i] = __ldg(ub + lane + 32 * i);
#pragma unroll
    for (int k = 0; k < 4; k++) {
        const float4* xr = x0 + (long)k * 256;
        float d = 0.f;
#pragma unroll
        for (int i = 0; i < 8; i++) {
            float4 xv = xr[lane + 32 * i];
            d += xv.x * uv[i].x + xv.y * uv[i].y + xv.z * uv[i].z + xv.w * uv[i].w;
        }
#pragma unroll
        for (int o = 16; o; o >>= 1) d += __shfl_xor_sync(0xffffffffu, d, o);
        if (lane == 0) sc[(long)b * S + tbase + k] = d * 0.03125f;  // 1/sqrt(1024)
    }
}

// ---------------- k3b: softmax (redundant per block) + weighted accumulate --
// grid ((S/128)*4, B), 256 thr. x re-read from L2. atomicAdd into xw (zeroed).
__global__ void __launch_bounds__(256) k3b(const float* __restrict__ x,
                                           const float* __restrict__ scg,
                                           float* __restrict__ xw, int S) {
    __shared__ float w[128];
    __shared__ float sbuf[32];
    __shared__ float4 redb[4][64];
    int b = blockIdx.y;
    int ntc = S >> 7;                                 // 128-token chunks
    int tc = blockIdx.x % ntc, jc = blockIdx.x / ntc; // jc in 0..3
    int tid = threadIdx.x;
    cudaGridDependencySynchronize();

    const float* sb = scg + (long)b * S;
    float m = -1e30f;
    for (int t = tid; t < S; t += 256) m = fmaxf(m, sb[t]);
    m = blk_rmax(m, sbuf);
    float s = 0.f;
    for (int t = tid; t < S; t += 256) s += __expf(sb[t] - m);
    s = blk_reduce(s, sbuf);
    float zinv = 1.f / s;
    if (tid < 128) w[tid] = __expf(sb[tc * 128 + tid] - m) * zinv;
    __syncthreads();

    int tg = tid >> 6, jj = tid & 63;
    int j4 = jc * 64 + jj;
    const float4* xb = (const float4*)x + ((long)b * S + tc * 128) * 256;
    float4 acc = make_float4(0.f, 0.f, 0.f, 0.f);
#pragma unroll 8
    for (int t = tg; t < 128; t += 4) {
        float p = w[t];
        float4 xv = xb[(long)t * 256 + j4];
        acc.x = fmaf(p, xv.x, acc.x);
        acc.y = fmaf(p, xv.y, acc.y);
        acc.z = fmaf(p, xv.z, acc.z);
        acc.w = fmaf(p, xv.w, acc.w);
    }
    redb[tg][jj] = acc;
    __syncthreads();
    if (tg == 0) {
        float4 t0 = redb[0][jj];
#pragma unroll
        for (int p = 1; p < 4; p++) {
            float4 v = redb[p][jj];
            t0.x += v.x; t0.y += v.y; t0.z += v.z; t0.w += v.w;
        }
        float* dst = &xw[(long)b * Dm + j4 * 4];
        atomicAdd(dst + 0, t0.x);
        atomicAdd(dst + 1, t0.y);
        atomicAdd(dst + 2, t0.z);
        atomicAdd(dst + 3, t0.w);
    }
}

// ---------------- r = LN1(accV + bv + x0); reset accV, xw --------------------
__global__ void __launch_bounds__(1024) k_ln1(float* __restrict__ acc,
                                              const float* __restrict__ x, long xstride,
                                              const float* __restrict__ bv,
                                              const float* __restrict__ g1,
                                              const float* __restrict__ b1,
                                              float* __restrict__ xwreset,
                                              float* __restrict__ r) {
    int b = blockIdx.x, j = threadIdx.x;
    __shared__ float sbuf[32];
    float gg = g1[j], bb = b1[j], bvj = bv[j];
    float x0j = x[(long)b * xstride + j];
    cudaGridDependencySynchronize();
    float v = acc[(long)b * Dm + j] + bvj + x0j;
    acc[(long)b * Dm + j] = 0.f;                      // reset for next replay
    xwreset[(long)b * Dm + j] = 0.f;                  // gemv(Wv) upstream done
    float sum = blk_reduce(v, sbuf);
    float sq  = blk_reduce(v * v, sbuf);
    float mu  = sum * (1.f / Dm);
    float var = sq * (1.f / Dm) - mu * mu;
    float rstd = rsqrtf(var + 1e-5f);
    r[(long)b * Dm + j] = (v - mu) * rstd * gg + bb;
}

// ---------------- h = LN2(relu(accD + bd) + r); logits; reset accD -----------
__global__ void __launch_bounds__(1024) k_ln2(float* __restrict__ acc,
                                              const float* __restrict__ bd,
                                              const float* __restrict__ r,
                                              const float* __restrict__ g2,
                                              const float* __restrict__ b2,
                                              const float* __restrict__ Wc,
                                              const float* __restrict__ bc,
                                              float* __restrict__ out) {
    int b = blockIdx.x, j = threadIdx.x;
    __shared__ float sbuf[32];
    float gg = g2[j], bb = b2[j], bdj = bd[j];
    float w0 = Wc[j * 2 + 0], w1 = Wc[j * 2 + 1];
    cudaGridDependencySynchronize();
    float v = fmaxf(acc[(long)b * Dm + j] + bdj, 0.f) + r[(long)b * Dm + j];
    acc[(long)b * Dm + j] = 0.f;                      // reset for next replay
    float sum = blk_reduce(v, sbuf);
    float sq  = blk_reduce(v * v, sbuf);
    float mu  = sum * (1.f / Dm);
    float var = sq * (1.f / Dm) - mu * mu;
    float rstd = rsqrtf(var + 1e-5f);
    float h = (v - mu) * rstd * gg + bb;
    float l0 = blk_reduce(h * w0, sbuf);
    float l1 = blk_reduce(h * w1, sbuf);
    if (j == 0) {
        out[b * 2 + 0] = l0 + bc[0];
        out[b * 2 + 1] = l1 + bc[1];
    }
}

// ---------------- host --------------------------------------------------------
static void launch_ex(const void* fn, dim3 grid, dim3 block, void** args, bool pdl) {
    cudaLaunchConfig_t cfg = {};
    cfg.gridDim = grid;
    cfg.blockDim = block;
    cfg.dynamicSmemBytes = 0;
    cfg.stream = 0;
    cudaLaunchAttribute attr[1];
    attr[0].id = cudaLaunchAttributeProgrammaticStreamSerialization;
    attr[0].val.programmaticStreamSerializationAllowed = 1;
    cfg.attrs = attr;
    cfg.numAttrs = pdl ? 1 : 0;
    cudaLaunchKernelExC(&cfg, fn, args);
}

extern "C" void kernel_launch(void* const* d_in, const int* in_sizes, int n_in,
                              void* d_out, int out_size) {
    const float* x  = (const float*)d_in[0];
    const float* Wq = (const float*)d_in[1];
    const float* bq = (const float*)d_in[2];
    const float* Wk = (const float*)d_in[3];
    // d_in[4] = bk: constant over t in scores -> cancels in softmax; unused.
    const float* Wv = (const float*)d_in[5];
    const float* bv = (const float*)d_in[6];
    const float* Wd = (const float*)d_in[7];
    const float* bd = (const float*)d_in[8];
    const float* g1 = (const float*)d_in[9];
    const float* b1 = (const float*)d_in[10];
    const float* g2 = (const float*)d_in[11];
    const float* b2 = (const float*)d_in[12];
    const float* Wc = (const float*)d_in[13];
    const float* bc = (const float*)d_in[14];
    float* out = (float*)d_out;

    int  B   = out_size / 2;                       // 8
    long xsz = (long)in_sizes[0];
    int  S   = (int)(xsz / ((long)B * Dm));        // 2048
    long xstride = (long)S * Dm;

    float *q0, *u, *xw, *r, *accV, *accD, *sc;
    cudaGetSymbolAddress((void**)&q0,   g_q0);
    cudaGetSymbolAddress((void**)&u,    g_u);
    cudaGetSymbolAddress((void**)&xw,   g_xw);
    cudaGetSymbolAddress((void**)&r,    g_r);
    cudaGetSymbolAddress((void**)&accV, g_accV);
    cudaGetSymbolAddress((void**)&accD, g_accD);
    cudaGetSymbolAddress((void**)&sc,   g_sc);

    // 1. q0 += x0 @ Wq   (first kernel: no PDL wait; starts loading at t=0)
    {
        void* a[] = {(void*)&x, (void*)&xstride, (void*)&Wq, (void*)&q0, (void*)&B};
        launch_ex((const void*)gemv_pdl, dim3(4, 32), dim3(256), a, false);
    }
    // 2. u = Wk @ (q0 + bq)
    {
        void* a[] = {(void*)&Wk, (void*)&q0, (void*)&bq, (void*)&u};
        launch_ex((const void*)k2_u, dim3(Dm / 8), dim3(256), a, true);
    }
    // 3. scores (also zeroes q0 for next replay)
    {
        void* a[] = {(void*)&x, (void*)&u, (void*)&q0, (void*)&sc, (void*)&S};
        launch_ex((const void*)k3a, dim3(S / 32, B), dim3(256), a, true);
    }
    // 4. softmax + weighted accumulate -> xw
    {
        void* a[] = {(void*)&x, (void*)&sc, (void*)&xw, (void*)&S};
        launch_ex((const void*)k3b, dim3((S / 128) * 4, B), dim3(256), a, true);
    }
    // 5. accV += xw @ Wv
    {
        long st = Dm;
        void* a[] = {(void*)&xw, (void*)&st, (void*)&Wv, (void*)&accV, (void*)&B};
        launch_ex((const void*)gemv_pdl, dim3(4, 32), dim3(256), a, true);
    }
    // 6. r = LN1(accV + bv + x0); zero accV, xw
    {
        void* a[] = {(void*)&accV, (void*)&x, (void*)&xstride, (void*)&bv,
                     (void*)&g1, (void*)&b1, (void*)&xw, (void*)&r};
        launch_ex((const void*)k_ln1, dim3(B), dim3(1024), a, true);
    }
    // 7. accD += r @ Wd
    {
        long st = Dm;
        void* a[] = {(void*)&r, (void*)&st, (void*)&Wd, (void*)&accD, (void*)&B};
        launch_ex((const void*)gemv_pdl, dim3(4, 32), dim3(256), a, true);
    }
    // 8. out = LN2(relu(accD + bd) + r) @ Wc + bc; zero accD
    {
        void* a[] = {(void*)&accD, (void*)&bd, (void*)&r, (void*)&g2, (void*)&b2,
                     (void*)&Wc, (void*)&bc, (void*)&out};
        launch_ex((const void*)k_ln2, dim3(B), dim3(1024), a, true);
    }
}